// round 3
// baseline (speedup 1.0000x reference)
#include <cuda_runtime.h>
#include <cstdint>

// ---------------------------------------------------------------------------
// SubsetOperator: output = one-hot(top_k(scores)) in fp32.
// See analysis: reference forward reduces exactly to this (non-selected lanes
// are exactly 0.0f; selected lanes are 1.0f within ~2 ulp; top_k(khot) ==
// top_k(scores) with margin ~6.5e-3 at the k-th boundary for this input).
// ---------------------------------------------------------------------------

#define SEG_ELEMS 2048            // elements per warp segment (one warp each)
#define SEG_F4    (SEG_ELEMS / 4) // 512 float4 per segment
#define MAX_SEGS  8192            // 16,777,216 / 2048
#define CAND_CAP  (1 << 20)
#define MAXK      1024

__device__ unsigned int       g_seg_max[MAX_SEGS];
__device__ unsigned long long g_cand[CAND_CAP];
__device__ int                g_cand_count;
__device__ unsigned int       g_thresh;
__device__ int                g_flag_count;
__device__ int                g_flag_segs[MAX_SEGS];
__device__ int                g_k;

// monotone mapping: fp32 total order -> uint32 order
__device__ __forceinline__ unsigned int fmono(float x) {
    unsigned int b = __float_as_uint(x);
    return b ^ ((unsigned int)((int)b >> 31) | 0x80000000u);
}

__device__ __forceinline__ unsigned long long umax64(unsigned long long a,
                                                     unsigned long long b) {
    return a > b ? a : b;
}

// ---------------------------------------------------------------------------
// Kernel 1: fused zero-fill of out + per-warp-segment max of fmono(scores).
// One warp owns one contiguous 2048-element segment; float4 coalesced.
// ---------------------------------------------------------------------------
__global__ void k1_segmax_zero(const float* __restrict__ scores,
                               float* __restrict__ out, int n, int nSeg) {
    int warpsPerBlock = blockDim.x >> 5;
    int seg  = blockIdx.x * warpsPerBlock + (threadIdx.x >> 5);
    int lane = threadIdx.x & 31;
    if (seg >= nSeg) return;

    const float4* s4 = (const float4*)scores;
    float4*       o4 = (float4*)out;
    int base4 = seg * SEG_F4;
    float4 z = make_float4(0.f, 0.f, 0.f, 0.f);
    unsigned int m = 0u;

#pragma unroll
    for (int j = 0; j < SEG_F4 / 32; ++j) {       // 16 iters per lane
        int idx4 = base4 + j * 32 + lane;
        int e0   = idx4 * 4;
        if (e0 + 3 < n) {
            float4 v = s4[idx4];
            o4[idx4] = z;
            unsigned int u0 = fmono(v.x), u1 = fmono(v.y);
            unsigned int u2 = fmono(v.z), u3 = fmono(v.w);
            unsigned int a = u0 > u1 ? u0 : u1;
            unsigned int b = u2 > u3 ? u2 : u3;
            unsigned int c = a > b ? a : b;
            if (c > m) m = c;
        } else {                                  // generic tail (unused for N=16M)
            for (int e = 0; e < 4; ++e) {
                int i = e0 + e;
                if (i < n) {
                    unsigned int u = fmono(scores[i]);
                    if (u > m) m = u;
                    out[i] = 0.f;
                }
            }
        }
    }
#pragma unroll
    for (int off = 16; off > 0; off >>= 1) {
        unsigned int o = __shfl_xor_sync(0xFFFFFFFFu, m, off);
        if (o > m) m = o;
    }
    if (lane == 0) g_seg_max[seg] = m;
}

// ---------------------------------------------------------------------------
// Kernel 2: single block. Select T = k-th largest segment max (any global
// top-k element is >= T). Flag segments with max >= T. Init counters.
// ---------------------------------------------------------------------------
__global__ void k2_select_thresh(const int* kptr, int nSeg) {
    __shared__ unsigned long long sred[1024];
    __shared__ unsigned long long s_prev;
    int tid = threadIdx.x;

    if (tid == 0) {
        g_flag_count = 0;
        g_cand_count = 0;
        int k = kptr ? *kptr : 32;
        if (k < 1) k = 1;
        if (k > MAXK) k = MAXK;
        g_k = k;
        s_prev = 0xFFFFFFFFFFFFFFFFULL;
    }
    __syncthreads();
    int k = g_k;

    // each thread owns 8 segments; keys unique: (u << 13) | seg
    unsigned long long mykeys[MAX_SEGS / 1024];
#pragma unroll
    for (int j = 0; j < MAX_SEGS / 1024; ++j) {
        int s = tid + j * 1024;
        unsigned int v = (s < nSeg) ? g_seg_max[s] : 0u;
        mykeys[j] = ((unsigned long long)v << 13) | (unsigned int)s;
    }

    for (int r = 0; r < k; ++r) {
        unsigned long long prev = s_prev;
        unsigned long long best = 0ULL;
#pragma unroll
        for (int j = 0; j < MAX_SEGS / 1024; ++j)
            if (mykeys[j] < prev && mykeys[j] > best) best = mykeys[j];
        sred[tid] = best;
        __syncthreads();
        for (int off = 512; off > 0; off >>= 1) {
            if (tid < off) sred[tid] = umax64(sred[tid], sred[tid + off]);
            __syncthreads();
        }
        if (tid == 0) s_prev = sred[0];
        __syncthreads();
    }

    unsigned int T = (unsigned int)(s_prev >> 13);
    if (tid == 0) g_thresh = T;

#pragma unroll
    for (int j = 0; j < MAX_SEGS / 1024; ++j) {
        int s = tid + j * 1024;
        if (s < nSeg && g_seg_max[s] >= T) {
            int p = atomicAdd(&g_flag_count, 1);
            g_flag_segs[p] = s;
        }
    }
}

// ---------------------------------------------------------------------------
// Kernel 3: re-scan only flagged segments (L2-hot, ~100 KB), collect
// candidates with u >= T. Key = (u << 32) | (~idx) -> max-by-key gives
// max value, ties broken by LOWEST index (matches lax.top_k).
// ---------------------------------------------------------------------------
__global__ void k3_collect(const float* __restrict__ scores, int n) {
    unsigned int T = g_thresh;
    int F = g_flag_count;
    for (int f = blockIdx.x; f < F; f += gridDim.x) {
        int base = g_flag_segs[f] * SEG_ELEMS;
        for (int t = threadIdx.x; t < SEG_ELEMS; t += blockDim.x) {
            int i = base + t;
            if (i < n) {
                unsigned int u = fmono(scores[i]);
                if (u >= T) {
                    int p = atomicAdd(&g_cand_count, 1);
                    if (p < CAND_CAP)
                        g_cand[p] = ((unsigned long long)u << 32) |
                                    (unsigned int)(0xFFFFFFFFu - (unsigned int)i);
                }
            }
        }
    }
}

// ---------------------------------------------------------------------------
// Kernel 4: single block. k rounds of block-max over candidate keys,
// write 1.0f at each selected index. Order-independent -> deterministic
// regardless of atomic append order.
// ---------------------------------------------------------------------------
__global__ void k4_write(float* __restrict__ out) {
    __shared__ unsigned long long sred[256];
    __shared__ unsigned long long s_prev;
    int tid = threadIdx.x;
    int C = g_cand_count;
    if (C > CAND_CAP) C = CAND_CAP;
    int k = g_k;
    if (tid == 0) s_prev = 0xFFFFFFFFFFFFFFFFULL;
    __syncthreads();

    for (int r = 0; r < k; ++r) {
        unsigned long long prev = s_prev;
        unsigned long long best = 0ULL;
        for (int j = tid; j < C; j += 256) {
            unsigned long long key = g_cand[j];
            if (key < prev && key > best) best = key;
        }
        sred[tid] = best;
        __syncthreads();
        for (int off = 128; off > 0; off >>= 1) {
            if (tid < off) sred[tid] = umax64(sred[tid], sred[tid + off]);
            __syncthreads();
        }
        if (tid == 0) {
            unsigned long long b = sred[0];
            s_prev = b;
            if (b != 0ULL) {
                unsigned int idx = 0xFFFFFFFFu - (unsigned int)(b & 0xFFFFFFFFu);
                out[idx] = 1.0f;
            }
        }
        __syncthreads();
    }
}

// ---------------------------------------------------------------------------
extern "C" void kernel_launch(void* const* d_in, const int* in_sizes, int n_in,
                              void* d_out, int out_size) {
    const float* scores = (const float*)d_in[0];
    int n = in_sizes[0];
    const int* kptr = nullptr;
    for (int i = 0; i < n_in; ++i) {
        if (in_sizes[i] == 1) {
            kptr = (const int*)d_in[i];
        } else {
            scores = (const float*)d_in[i];
            n = in_sizes[i];
        }
    }
    float* out = (float*)d_out;

    int nSeg = (n + SEG_ELEMS - 1) / SEG_ELEMS;     // 8192 for N = 16,777,216
    if (nSeg > MAX_SEGS) nSeg = MAX_SEGS;           // (not hit for this problem)

    int warpsPerBlock = 8;                          // 256 threads
    int blocks1 = (nSeg + warpsPerBlock - 1) / warpsPerBlock;

    k1_segmax_zero<<<blocks1, 256>>>(scores, out, n, nSeg);
    k2_select_thresh<<<1, 1024>>>(kptr, nSeg);
    k3_collect<<<128, 256>>>(scores, n);
    k4_write<<<1, 256>>>(out);
}

// round 4
// speedup vs baseline: 1.3571x; 1.3571x over previous
#include <cuda_runtime.h>
#include <cstdint>

// ---------------------------------------------------------------------------
// SubsetOperator: output = one-hot(top_k(scores)) in fp32.
// Forward of the reference reduces exactly to this: non-selected lanes are
// exactly 0.0f ((0-x)+x == 0 in fp32), selected are 1.0f within ~2 ulp, and
// top_k(khot) == top_k(scores) (boundary margin ~6.5e-3 >> perturbations).
//
// Two kernels:
//   kA: zero out + per-warp-segment max of fmono(scores)    [HBM-bound pass]
//       last block: histogram-select threshold T (bin floor of k-th segmax)
//   kB: warps rescan only segments with segmax >= T, collect candidates;
//       last block: O(C^2) parallel ranking, write 1.0f at top-k indices.
// ---------------------------------------------------------------------------

#define SEG_ELEMS 2048
#define SEG_F4    (SEG_ELEMS / 4)
#define MAX_SEGS  8192
#define CAND_CAP  (1 << 20)
#define SMEM_KEYS 4096            // 32 KB smem key cache for ranking
#define MAXK      1024
#define TPB       512             // 16 warps / block
#define HIST_SHIFT 19             // top 13 bits -> 8192 bins

__device__ unsigned int       g_seg_max[MAX_SEGS];
__device__ unsigned long long g_cand[CAND_CAP];
__device__ int                g_cand_count;
__device__ unsigned int       g_thresh;
__device__ int                g_k;
__device__ unsigned int       g_done_a;   // zero-initialized; reset by last block
__device__ unsigned int       g_done_b;

// monotone mapping: fp32 total order -> uint32 order
__device__ __forceinline__ unsigned int fmono(float x) {
    unsigned int b = __float_as_uint(x);
    return b ^ ((unsigned int)((int)b >> 31) | 0x80000000u);
}

// ---------------------------------------------------------------------------
// Kernel A: fused zero-fill + per-warp segment max; last block selects T.
// ---------------------------------------------------------------------------
__global__ void kA(const float* __restrict__ scores, float* __restrict__ out,
                   const int* kptr, int n, int nSeg, int nBlocks) {
    int warp = threadIdx.x >> 5;
    int lane = threadIdx.x & 31;
    int seg  = blockIdx.x * (TPB / 32) + warp;

    if (seg < nSeg) {
        const float4* s4 = (const float4*)scores;
        float4*       o4 = (float4*)out;
        int base4 = seg * SEG_F4;
        float4 z = make_float4(0.f, 0.f, 0.f, 0.f);
        unsigned int m = 0u;

#pragma unroll
        for (int j = 0; j < SEG_F4 / 32; ++j) {       // 16 iters per lane
            int idx4 = base4 + j * 32 + lane;
            int e0   = idx4 * 4;
            if (e0 + 3 < n) {
                float4 v = s4[idx4];
                o4[idx4] = z;
                unsigned int u0 = fmono(v.x), u1 = fmono(v.y);
                unsigned int u2 = fmono(v.z), u3 = fmono(v.w);
                unsigned int a = u0 > u1 ? u0 : u1;
                unsigned int b = u2 > u3 ? u2 : u3;
                unsigned int c = a > b ? a : b;
                if (c > m) m = c;
            } else {                                   // generic tail
                for (int e = 0; e < 4; ++e) {
                    int i = e0 + e;
                    if (i < n) {
                        unsigned int u = fmono(scores[i]);
                        if (u > m) m = u;
                        out[i] = 0.f;
                    }
                }
            }
        }
#pragma unroll
        for (int off = 16; off > 0; off >>= 1) {
            unsigned int o = __shfl_xor_sync(0xFFFFFFFFu, m, off);
            if (o > m) m = o;
        }
        if (lane == 0) g_seg_max[seg] = m;
    }

    // ---- last-block-done: threshold selection rides the kernel tail ----
    __shared__ unsigned int is_last;
    __threadfence();
    __syncthreads();
    if (threadIdx.x == 0)
        is_last = (atomicAdd(&g_done_a, 1u) == (unsigned int)(nBlocks - 1));
    __syncthreads();
    if (!is_last) return;
    __threadfence();

    int k = 32;
    if (kptr) k = *kptr;
    if (k < 1) k = 1;
    if (k > MAXK) k = MAXK;

    __shared__ unsigned int hist[MAX_SEGS];
    __shared__ unsigned int ssum[TPB];

    for (int j = threadIdx.x; j < MAX_SEGS; j += TPB) hist[j] = 0u;
    __syncthreads();
    for (int j = threadIdx.x; j < nSeg; j += TPB)
        atomicAdd(&hist[g_seg_max[j] >> HIST_SHIFT], 1u);
    __syncthreads();

    // thread t owns bins [t*16, t*16+16); compute its total
    int b0 = threadIdx.x * (MAX_SEGS / TPB);
    unsigned int tot = 0u;
#pragma unroll
    for (int j = 0; j < MAX_SEGS / TPB; ++j) tot += hist[b0 + j];
    ssum[threadIdx.x] = tot;
    __syncthreads();

    // inclusive suffix scan (Hillis-Steele, 9 steps)
    for (int off = 1; off < TPB; off <<= 1) {
        unsigned int v = (threadIdx.x + off < TPB) ? ssum[threadIdx.x + off] : 0u;
        __syncthreads();
        ssum[threadIdx.x] += v;
        __syncthreads();
    }
    // exclusive suffix for this thread = inclusive suffix of thread t+1
    unsigned int run = (threadIdx.x + 1 < TPB) ? ssum[threadIdx.x + 1] : 0u;

    // walk own bins high -> low; the unique bin crossing count k is the bin
    // containing the k-th largest segment max. T = its floor.
#pragma unroll
    for (int j = MAX_SEGS / TPB - 1; j >= 0; --j) {
        unsigned int h = hist[b0 + j];
        unsigned int nr = run + h;
        if (run < (unsigned int)k && nr >= (unsigned int)k)
            g_thresh = ((unsigned int)(b0 + j)) << HIST_SHIFT;
        run = nr;
    }

    if (threadIdx.x == 0) {
        g_k = k;
        g_cand_count = 0;
        g_done_a = 0;     // reset for next graph replay
    }
}

// ---------------------------------------------------------------------------
// Kernel B: collect candidates from flagged segments; last block ranks and
// writes 1.0f at the top-k indices (order-independent -> deterministic).
// ---------------------------------------------------------------------------
__global__ void kB(const float* __restrict__ scores, float* __restrict__ out,
                   int n, int nSeg, int nBlocks) {
    unsigned int T = g_thresh;
    int warp = threadIdx.x >> 5;
    int lane = threadIdx.x & 31;
    int seg  = blockIdx.x * (TPB / 32) + warp;

    if (seg < nSeg && g_seg_max[seg] >= T) {
        int base = seg * SEG_ELEMS;
        for (int j = lane; j < SEG_ELEMS; j += 32) {
            int i = base + j;
            if (i < n) {
                unsigned int u = fmono(scores[i]);
                if (u >= T) {
                    int p = atomicAdd(&g_cand_count, 1);
                    if (p < CAND_CAP)
                        g_cand[p] = ((unsigned long long)u << 32) |
                                    (unsigned int)(0xFFFFFFFFu - (unsigned int)i);
                }
            }
        }
    }

    // ---- last-block-done: ranking rides the kernel tail ----
    __shared__ unsigned int is_last;
    __threadfence();
    __syncthreads();
    if (threadIdx.x == 0)
        is_last = (atomicAdd(&g_done_b, 1u) == (unsigned int)(nBlocks - 1));
    __syncthreads();
    if (!is_last) return;
    __threadfence();

    int C = g_cand_count;
    if (C > CAND_CAP) C = CAND_CAP;
    int k = g_k;

    __shared__ unsigned long long skeys[SMEM_KEYS];
    if (C <= SMEM_KEYS) {
        for (int j = threadIdx.x; j < C; j += TPB) skeys[j] = g_cand[j];
        __syncthreads();
        for (int j = threadIdx.x; j < C; j += TPB) {
            unsigned long long kj = skeys[j];
            int rank = 0;
            for (int i = 0; i < C; ++i) rank += (skeys[i] > kj);
            if (rank < k)
                out[0xFFFFFFFFu - (unsigned int)(kj & 0xFFFFFFFFu)] = 1.0f;
        }
    } else {
        // fallback (never hit for this data); correct but slower
        for (int j = threadIdx.x; j < C; j += TPB) {
            unsigned long long kj = g_cand[j];
            int rank = 0;
            for (int i = 0; i < C; ++i) rank += (g_cand[i] > kj);
            if (rank < k)
                out[0xFFFFFFFFu - (unsigned int)(kj & 0xFFFFFFFFu)] = 1.0f;
        }
    }

    if (threadIdx.x == 0) g_done_b = 0;   // reset for next graph replay
}

// ---------------------------------------------------------------------------
extern "C" void kernel_launch(void* const* d_in, const int* in_sizes, int n_in,
                              void* d_out, int out_size) {
    const float* scores = (const float*)d_in[0];
    int n = in_sizes[0];
    const int* kptr = nullptr;
    for (int i = 0; i < n_in; ++i) {
        if (in_sizes[i] == 1) {
            kptr = (const int*)d_in[i];
        } else {
            scores = (const float*)d_in[i];
            n = in_sizes[i];
        }
    }
    float* out = (float*)d_out;

    int nSeg = (n + SEG_ELEMS - 1) / SEG_ELEMS;    // 8192 for N = 16,777,216
    if (nSeg > MAX_SEGS) nSeg = MAX_SEGS;

    int warpsPerBlock = TPB / 32;                  // 16
    int nBlocks = (nSeg + warpsPerBlock - 1) / warpsPerBlock;   // 512

    kA<<<nBlocks, TPB>>>(scores, out, kptr, n, nSeg, nBlocks);
    kB<<<nBlocks, TPB>>>(scores, out, n, nSeg, nBlocks);
}

// round 5
// speedup vs baseline: 2.3487x; 1.7307x over previous
#include <cuda_runtime.h>
#include <cstdint>

// ---------------------------------------------------------------------------
// SubsetOperator: output = one-hot(top_k(scores)) in fp32.
// The reference forward reduces exactly to this (non-selected lanes exactly
// 0.0f, selected 1.0f within ~2 ulp; top_k(khot)==top_k(scores), boundary
// margin ~6.5e-3 >> all perturbations).
//
// R4: removed all grid-wide last-block protocols (gpu membar + same-address
// atomics across 512 blocks were the 36us cost). Threshold selection now runs
// over 512 block-maxima (trivial histogram) in a tiny single-block kernel.
// ---------------------------------------------------------------------------

#define SEG_ELEMS 2048
#define SEG_F4    (SEG_ELEMS / 4)
#define MAX_SEGS  8192
#define MAX_BLKA  512
#define CAND_CAP  (1 << 20)
#define SMEM_KEYS 4096
#define MAXK      1024
#define TPB_A     512
#define WARPS_A   (TPB_A / 32)
#define HIST_BINS 8192
#define HIST_SHIFT 19            // top 13 bits of fmono -> 8192 bins

__device__ unsigned int       g_seg_max[MAX_SEGS];
__device__ unsigned int       g_blk_max[MAX_BLKA];
__device__ unsigned long long g_cand[CAND_CAP];
__device__ int                g_cand_count;
__device__ unsigned int       g_thresh;
__device__ int                g_k;
__device__ int                g_flag_count;
__device__ int                g_flag_segs[MAX_SEGS];

// monotone mapping: fp32 total order -> uint32 order
__device__ __forceinline__ unsigned int fmono(float x) {
    unsigned int b = __float_as_uint(x);
    return b ^ ((unsigned int)((int)b >> 31) | 0x80000000u);
}

// ---------------------------------------------------------------------------
// kA: fused zero-fill + per-warp segment max + per-block max. Pure pass,
// no cross-block synchronization of any kind.
// ---------------------------------------------------------------------------
__global__ void kA(const float* __restrict__ scores, float* __restrict__ out,
                   int n, int nSeg) {
    __shared__ unsigned int wmax[WARPS_A];
    int warp = threadIdx.x >> 5;
    int lane = threadIdx.x & 31;
    int seg  = blockIdx.x * WARPS_A + warp;

    unsigned int m = 0u;
    if (seg < nSeg) {
        const float4* s4 = (const float4*)scores;
        float4*       o4 = (float4*)out;
        int base4 = seg * SEG_F4;
        float4 z = make_float4(0.f, 0.f, 0.f, 0.f);

#pragma unroll
        for (int j = 0; j < SEG_F4 / 32; ++j) {       // 16 iters per lane
            int idx4 = base4 + j * 32 + lane;
            int e0   = idx4 * 4;
            if (e0 + 3 < n) {
                float4 v = s4[idx4];
                o4[idx4] = z;
                unsigned int u0 = fmono(v.x), u1 = fmono(v.y);
                unsigned int u2 = fmono(v.z), u3 = fmono(v.w);
                unsigned int a = u0 > u1 ? u0 : u1;
                unsigned int b = u2 > u3 ? u2 : u3;
                unsigned int c = a > b ? a : b;
                if (c > m) m = c;
            } else {                                   // generic tail
                for (int e = 0; e < 4; ++e) {
                    int i = e0 + e;
                    if (i < n) {
                        unsigned int u = fmono(scores[i]);
                        if (u > m) m = u;
                        out[i] = 0.f;
                    }
                }
            }
        }
#pragma unroll
        for (int off = 16; off > 0; off >>= 1) {
            unsigned int o = __shfl_xor_sync(0xFFFFFFFFu, m, off);
            if (o > m) m = o;
        }
        if (lane == 0) g_seg_max[seg] = m;
    }
    if (lane == 0) wmax[warp] = m;
    __syncthreads();
    if (warp == 0) {
        unsigned int v = (lane < WARPS_A) ? wmax[lane] : 0u;
#pragma unroll
        for (int off = 8; off > 0; off >>= 1) {
            unsigned int o = __shfl_xor_sync(0xFFFFFFFFu, v, off);
            if (o > v) v = o;
        }
        if (lane == 0) g_blk_max[blockIdx.x] = v;
    }
}

// ---------------------------------------------------------------------------
// kS: single block. Histogram-select T = bin floor of the k-th largest
// block-max (valid threshold: >=k blocks each contribute >=1 element >= T).
// Then flag segments with segmax >= T; init counters for this replay.
// ---------------------------------------------------------------------------
__global__ void kS(const int* kptr, int nSeg, int nBlkA) {
    __shared__ unsigned int hist[HIST_BINS];
    __shared__ unsigned int ssum[1024];
    __shared__ int s_k;
    __shared__ unsigned int s_T;
    int tid = threadIdx.x;

    if (tid == 0) {
        int k = kptr ? *kptr : 32;
        if (k < 1) k = 1;
        if (k > MAXK) k = MAXK;
        s_k = k;
        s_T = 0u;                 // fallback if k exceeds available maxima
        g_flag_count = 0;
        g_cand_count = 0;
    }
    __syncthreads();
    int k = s_k;

    // source of maxima: block-maxes (512, cheap) unless k exceeds them
    const unsigned int* src = (k <= nBlkA) ? g_blk_max : g_seg_max;
    int cnt = (k <= nBlkA) ? nBlkA : nSeg;

    for (int j = tid; j < HIST_BINS; j += 1024) hist[j] = 0u;
    __syncthreads();
    for (int j = tid; j < cnt; j += 1024)
        atomicAdd(&hist[src[j] >> HIST_SHIFT], 1u);
    __syncthreads();

    // per-thread totals over 8 owned bins, then suffix scan
    int b0 = tid * (HIST_BINS / 1024);
    unsigned int tot = 0u;
#pragma unroll
    for (int j = 0; j < HIST_BINS / 1024; ++j) tot += hist[b0 + j];
    ssum[tid] = tot;
    __syncthreads();
    for (int off = 1; off < 1024; off <<= 1) {
        unsigned int v = (tid + off < 1024) ? ssum[tid + off] : 0u;
        __syncthreads();
        ssum[tid] += v;
        __syncthreads();
    }
    unsigned int run = (tid + 1 < 1024) ? ssum[tid + 1] : 0u;
#pragma unroll
    for (int j = HIST_BINS / 1024 - 1; j >= 0; --j) {
        unsigned int h = hist[b0 + j];
        if (run < (unsigned int)k && run + h >= (unsigned int)k)
            s_T = ((unsigned int)(b0 + j)) << HIST_SHIFT;   // unique crossing
        run += h;
    }
    __syncthreads();

    unsigned int T = s_T;
    if (tid == 0) { g_thresh = T; g_k = k; }

    for (int j = tid; j < nSeg; j += 1024) {
        if (g_seg_max[j] >= T) {
            int p = atomicAdd(&g_flag_count, 1);
            g_flag_segs[p] = j;
        }
    }
}

// ---------------------------------------------------------------------------
// kC: collect candidates >= T from flagged segments only (L2-hot, ~230 KB).
// Key = (u << 32) | ~idx  -> larger key = larger value, ties -> lower index
// (matches lax.top_k ordering).
// ---------------------------------------------------------------------------
__global__ void kC(const float* __restrict__ scores, int n) {
    unsigned int T = g_thresh;
    int F = g_flag_count;
    const float4* s4 = (const float4*)scores;

    for (int f = blockIdx.x; f < F; f += gridDim.x) {
        int base4 = g_flag_segs[f] * SEG_F4;
        for (int t = threadIdx.x; t < SEG_F4; t += blockDim.x) {
            int idx4 = base4 + t;
            int e0   = idx4 * 4;
            if (e0 + 3 < n) {
                float4 v = s4[idx4];
                unsigned int u[4] = {fmono(v.x), fmono(v.y), fmono(v.z), fmono(v.w)};
#pragma unroll
                for (int e = 0; e < 4; ++e) {
                    if (u[e] >= T) {
                        int p = atomicAdd(&g_cand_count, 1);
                        if (p < CAND_CAP)
                            g_cand[p] = ((unsigned long long)u[e] << 32) |
                                        (unsigned int)(0xFFFFFFFFu - (unsigned int)(e0 + e));
                    }
                }
            } else {
                for (int e = 0; e < 4; ++e) {
                    int i = e0 + e;
                    if (i < n) {
                        unsigned int u = fmono(scores[i]);
                        if (u >= T) {
                            int p = atomicAdd(&g_cand_count, 1);
                            if (p < CAND_CAP)
                                g_cand[p] = ((unsigned long long)u << 32) |
                                            (unsigned int)(0xFFFFFFFFu - (unsigned int)i);
                        }
                    }
                }
            }
        }
    }
}

// ---------------------------------------------------------------------------
// kD: single block. O(C^2) rank over unique keys; write 1.0f at top-k.
// Order-independent -> deterministic regardless of atomic append order.
// ---------------------------------------------------------------------------
__global__ void kD(float* __restrict__ out) {
    __shared__ unsigned long long skeys[SMEM_KEYS];
    int tid = threadIdx.x;
    int C = g_cand_count;
    if (C > CAND_CAP) C = CAND_CAP;
    int k = g_k;

    if (C <= SMEM_KEYS) {
        for (int j = tid; j < C; j += blockDim.x) skeys[j] = g_cand[j];
        __syncthreads();
        for (int j = tid; j < C; j += blockDim.x) {
            unsigned long long kj = skeys[j];
            int rank = 0;
            for (int i = 0; i < C; ++i) rank += (skeys[i] > kj);
            if (rank < k)
                out[0xFFFFFFFFu - (unsigned int)(kj & 0xFFFFFFFFu)] = 1.0f;
        }
    } else {   // fallback, never hit for this data
        for (int j = tid; j < C; j += blockDim.x) {
            unsigned long long kj = g_cand[j];
            int rank = 0;
            for (int i = 0; i < C; ++i) rank += (g_cand[i] > kj);
            if (rank < k)
                out[0xFFFFFFFFu - (unsigned int)(kj & 0xFFFFFFFFu)] = 1.0f;
        }
    }
}

// ---------------------------------------------------------------------------
extern "C" void kernel_launch(void* const* d_in, const int* in_sizes, int n_in,
                              void* d_out, int out_size) {
    const float* scores = (const float*)d_in[0];
    int n = in_sizes[0];
    const int* kptr = nullptr;
    for (int i = 0; i < n_in; ++i) {
        if (in_sizes[i] == 1) {
            kptr = (const int*)d_in[i];
        } else {
            scores = (const float*)d_in[i];
            n = in_sizes[i];
        }
    }
    float* out = (float*)d_out;

    int nSeg = (n + SEG_ELEMS - 1) / SEG_ELEMS;        // 8192 for N = 16,777,216
    if (nSeg > MAX_SEGS) nSeg = MAX_SEGS;
    int nBlkA = (nSeg + WARPS_A - 1) / WARPS_A;        // 512
    if (nBlkA > MAX_BLKA) nBlkA = MAX_BLKA;

    kA<<<nBlkA, TPB_A>>>(scores, out, n, nSeg);
    kS<<<1, 1024>>>(kptr, nSeg, nBlkA);
    kC<<<128, 256>>>(scores, n);
    kD<<<1, 256>>>(out);
}